// round 16
// baseline (speedup 1.0000x reference)
#include <cuda_runtime.h>
#include <math.h>
#include <stdint.h>

// Problem constants
#define BN   4
#define CN   256
#define HN   64
#define WN   64
#define HWN  4096
#define CHWN (CN * HWN)     // 1048576
#define SCALE 0.0625f       // 1/sqrt(256)

// int8 quantization: Q,K in [-2,2] (6.2 sigma), 63.5 LSB per unit
#define QMUL 63.5f
#define DEQ  (SCALE / (QMUL * QMUL))   // fold 1/sqrt(C) into dequant

// ---------------------------------------------------------------------------
// Scratch (device globals; no allocations allowed)
// ---------------------------------------------------------------------------
__device__ float    g_V [BN * CHWN];         // fp32 V, [b][c][n]
__device__ uint8_t  g_Q8[BN * CHWN];         // int8 Q, TRANSPOSED [b][n][c]
__device__ uint8_t  g_K8[BN * CHWN];         // int8 K, TRANSPOSED [b][m][c]
__device__ uint32_t g_QmaskU[4 * HWN];       // order-keyed Q_mask, (c%4)*4096+n
__device__ float    g_m2[BN * HN];           // int-keyed positive floats, b*64+h_k

__device__ __forceinline__ void cpasync16(void* dst, const void* src) {
    unsigned s = (unsigned)__cvta_generic_to_shared(dst);
    asm volatile("cp.async.cg.shared.global [%0], [%1], 16;\n" :: "r"(s), "l"(src));
}
__device__ __forceinline__ void cpcommit() { asm volatile("cp.async.commit_group;\n"); }
__device__ __forceinline__ void cpwait0()  { asm volatile("cp.async.wait_group 0;\n"); }

__device__ __forceinline__ void ldmx4(uint32_t& r0, uint32_t& r1, uint32_t& r2, uint32_t& r3,
                                      uint32_t addr) {
    asm volatile("ldmatrix.sync.aligned.m8n8.x4.shared.b16 {%0,%1,%2,%3}, [%4];"
                 : "=r"(r0), "=r"(r1), "=r"(r2), "=r"(r3) : "r"(addr));
}

__device__ __forceinline__ uint32_t tf32c(float x) {
    uint32_t r;
    asm("cvt.rna.tf32.f32 %0, %1;" : "=r"(r) : "f"(x));
    return r;
}
// pack two floats into bf16x2: lo = first arg
__device__ __forceinline__ uint32_t bf2(float lo, float hi) {
    uint32_t r;
    asm("cvt.rn.bf16x2.f32 %0, %1, %2;" : "=r"(r) : "f"(hi), "f"(lo));
    return r;
}
__device__ __forceinline__ int q8(float x) {
    int v = __float2int_rn(x * QMUL);
    return max(-127, min(127, v));
}
// order-preserving float <-> uint key (handles negatives)
__device__ __forceinline__ uint32_t fkey(float f) {
    uint32_t b = __float_as_uint(f);
    return b ^ (uint32_t)(((int)b >> 31) | 0x80000000);
}
__device__ __forceinline__ float funkey(uint32_t u) {
    uint32_t b = (u & 0x80000000u) ? (u ^ 0x80000000u) : ~u;
    return __uint_as_float(b);
}

// ---------------------------------------------------------------------------
// 0) zero QmaskU and m2 each call (atomics accumulate into them)
// ---------------------------------------------------------------------------
__global__ void init_kernel() {
    int i = blockIdx.x * blockDim.x + threadIdx.x;
    if (i < 4 * HWN) g_QmaskU[i] = 0u;
    if (i < BN * HN)  g_m2[i] = 0.0f;
}

// ---------------------------------------------------------------------------
// 1) fused QKV 1x1-conv GEMM on tensor cores.
//    Q,K: bf16 m16n8k16 (int8-quantized after, bf16 error negligible vs that).
//    V:   tf32 m16n8k8 (fp32-precision path to the output).
//    Block 64(o) x 64(n) per b; 8 warps = 4 o-tiles x 2 n-halves.
//    Epilogue: smem-staged coalesced stores for V/Q8/K8; Q_mask reduce.
// ---------------------------------------------------------------------------
#define QKC  16
#define FPCH 72                          // fuse smem pitch (floats)
#define WPCH 20                          // W smem pitch (floats)
#define FST  (QKC * FPCH)                // 1152
#define WST  (64 * WPCH)                 // 1280 per gemm
#define QSTG (FST + 3 * WST)             // 4992 floats per stage
#define QKV_SMEM ((2 * QSTG + 256) * 4)

__global__ __launch_bounds__(256, 2) void qkv_kernel(
    const float* __restrict__ fuse,
    const float* __restrict__ Wq, const float* __restrict__ bq,
    const float* __restrict__ Wk, const float* __restrict__ bk,
    const float* __restrict__ Wv, const float* __restrict__ bv)
{
    extern __shared__ float smemf[];
    uint32_t* sRedU = (uint32_t*)(smemf + 2 * QSTG);   // [4][64]

    const int b  = blockIdx.z;
    const int o0 = blockIdx.y * 64;
    const int n0 = blockIdx.x * 64;
    const int tid = threadIdx.x;
    const int warp = tid >> 5;
    const int lane = tid & 31;
    const int gid = lane >> 2;    // 0..7
    const int tg  = lane & 3;     // 0..3
    const int wo = warp & 3;      // o-tile (16 rows each)
    const int wm = warp >> 2;     // n-half (32 cols each)

    sRedU[tid] = 0u;

    const float* Wg[3] = {Wq, Wk, Wv};

    float acc[3][4][4];           // [gemm: 0=Q,1=K,2=V][j(n8 tile)][e]
#pragma unroll
    for (int g = 0; g < 3; g++)
#pragma unroll
        for (int j = 0; j < 4; j++)
#pragma unroll
            for (int e = 0; e < 4; e++) acc[g][j][e] = 0.f;

    // ---- async load of one K-chunk (16 c) into stage s ----
    auto issue_chunk = [&](int c, int s) {
        const int c0 = c * QKC;
        float* stg = smemf + s * QSTG;
        {   // fuse tile [16 k][64 n]: 1 float4/thread
            int k  = tid >> 4;
            int n4 = (tid & 15) * 4;
            cpasync16(&stg[k * FPCH + n4],
                      &fuse[(size_t)b * CHWN + (size_t)(c0 + k) * HWN + n0 + n4]);
        }
        {   // W tiles [64 o][16 k] row-major, 1 float4/thread/gemm
            int o  = tid >> 2;
            int k4 = (tid & 3) * 4;
#pragma unroll
            for (int g = 0; g < 3; g++)
                cpasync16(&stg[FST + g * WST + o * WPCH + k4],
                          &Wg[g][(size_t)(o0 + o) * CN + c0 + k4]);
        }
    };

    issue_chunk(0, 0);
    cpcommit();

    const int arow  = wo * 16 + gid;
    const int bcol0 = wm * 32 + gid;

    for (int c = 0; c < CN / QKC; c++) {
        cpwait0();
        __syncthreads();
        if (c < CN / QKC - 1) { issue_chunk(c + 1, (c + 1) & 1); cpcommit(); }

        const float* stg = smemf + (c & 1) * QSTG;
        const float* sF  = stg;
        const float* sW  = stg + FST;

        // ---- bf16 path: Q,K, one m16n8k16 per j per gemm (k = whole chunk) ----
        {
            uint32_t Bh[4][2];
#pragma unroll
            for (int j = 0; j < 4; j++) {
                const int col = bcol0 + j * 8;
                Bh[j][0] = bf2(sF[(2 * tg    ) * FPCH + col], sF[(2 * tg + 1) * FPCH + col]);
                Bh[j][1] = bf2(sF[(2 * tg + 8) * FPCH + col], sF[(2 * tg + 9) * FPCH + col]);
            }
#pragma unroll
            for (int g = 0; g < 2; g++) {
                const float* w = sW + g * WST;
                float2 a0 = *(const float2*)&w[(arow    ) * WPCH + 2 * tg];
                float2 a1 = *(const float2*)&w[(arow + 8) * WPCH + 2 * tg];
                float2 a2 = *(const float2*)&w[(arow    ) * WPCH + 2 * tg + 8];
                float2 a3 = *(const float2*)&w[(arow + 8) * WPCH + 2 * tg + 8];
                uint32_t A0 = bf2(a0.x, a0.y), A1 = bf2(a1.x, a1.y);
                uint32_t A2 = bf2(a2.x, a2.y), A3 = bf2(a3.x, a3.y);
#pragma unroll
                for (int j = 0; j < 4; j++) {
                    asm volatile(
                        "mma.sync.aligned.m16n8k16.row.col.f32.bf16.bf16.f32 "
                        "{%0,%1,%2,%3}, {%4,%5,%6,%7}, {%8,%9}, {%0,%1,%2,%3};"
                        : "+f"(acc[g][j][0]), "+f"(acc[g][j][1]),
                          "+f"(acc[g][j][2]), "+f"(acc[g][j][3])
                        : "r"(A0), "r"(A1), "r"(A2), "r"(A3),
                          "r"(Bh[j][0]), "r"(Bh[j][1]));
                }
            }
        }

        // ---- tf32 path: V only, two k8 steps ----
#pragma unroll
        for (int kk = 0; kk < QKC; kk += 8) {
            uint32_t Bc[4][2];
#pragma unroll
            for (int j = 0; j < 4; j++) {
                Bc[j][0] = tf32c(sF[(kk + tg    ) * FPCH + bcol0 + j * 8]);
                Bc[j][1] = tf32c(sF[(kk + tg + 4) * FPCH + bcol0 + j * 8]);
            }
            const float* w = sW + 2 * WST;
            uint32_t A0 = tf32c(w[(arow    ) * WPCH + kk + tg]);
            uint32_t A1 = tf32c(w[(arow + 8) * WPCH + kk + tg]);
            uint32_t A2 = tf32c(w[(arow    ) * WPCH + kk + tg + 4]);
            uint32_t A3 = tf32c(w[(arow + 8) * WPCH + kk + tg + 4]);
#pragma unroll
            for (int j = 0; j < 4; j++) {
                asm volatile(
                    "mma.sync.aligned.m16n8k8.row.col.f32.tf32.tf32.f32 "
                    "{%0,%1,%2,%3}, {%4,%5,%6,%7}, {%8,%9}, {%0,%1,%2,%3};"
                    : "+f"(acc[2][j][0]), "+f"(acc[2][j][1]),
                      "+f"(acc[2][j][2]), "+f"(acc[2][j][3])
                    : "r"(A0), "r"(A1), "r"(A2), "r"(A3),
                      "r"(Bc[j][0]), "r"(Bc[j][1]));
            }
        }
    }

    // ---- epilogue: stage V/Q8/K8 in smem, then coalesced global stores ----
    __syncthreads();                       // all compute done; stages reusable
    float*   epV = smemf;                  // [64 o][64 n] fp32 (16 KB)
    uint8_t* epQ = (uint8_t*)smemf + 16384;// [64 n][64 o] u8 (4 KB)
    uint8_t* epK = (uint8_t*)smemf + 20480;// [64 n][64 o] u8 (4 KB)

    const int oA = o0 + wo * 16 + gid;
    const int oB = oA + 8;
    const float bq0 = bq[oA], bq1 = bq[oB];
    const float bk0 = bk[oA], bk1 = bk[oB];
    const float bv0 = bv[oA], bv1 = bv[oB];
    const int cm = gid & 3;
    const int rA = wo * 16 + gid, rB = rA + 8;

#pragma unroll
    for (int j = 0; j < 4; j++) {
#pragma unroll
        for (int p = 0; p < 2; p++) {
            const int nl = wm * 32 + j * 8 + tg * 2 + p;
            float q0 = acc[0][j][p]     + bq0;
            float q1 = acc[0][j][2 + p] + bq1;
            float k0 = acc[1][j][p]     + bk0;
            float k1 = acc[1][j][2 + p] + bk1;
            float v0 = acc[2][j][p]     + bv0;
            float v1 = acc[2][j][2 + p] + bv1;
            epV[rA * 64 + nl] = v0;
            epV[rB * 64 + nl] = v1;
            epQ[nl * 64 + rA] = (uint8_t)(q8(q0) & 0xFF);
            epQ[nl * 64 + rB] = (uint8_t)(q8(q1) & 0xFF);
            epK[nl * 64 + rA] = (uint8_t)(q8(k0) & 0xFF);
            epK[nl * 64 + rB] = (uint8_t)(q8(k1) & 0xFF);
            atomicMax(&sRedU[cm * 64 + nl], fkey(fmaxf(q0, q1)));
        }
    }
    __syncthreads();

    // V: 1024 float4 slots (64 o-rows x 16 segs)
#pragma unroll
    for (int i = 0; i < 4; i++) {
        int slot = i * 256 + tid;
        int row = slot >> 4, seg = slot & 15;
        float4 v = ((const float4*)epV)[slot];
        *(float4*)&g_V[(size_t)b * CHWN + (size_t)(o0 + row) * HWN + n0 + seg * 4] = v;
    }
    // Q8/K8: 256 uint4 slots (64 n-rows x 4 segs)
    {
        int row = tid >> 2, seg = tid & 3;
        uint4 qv = ((const uint4*)epQ)[tid];
        uint4 kv = ((const uint4*)epK)[tid];
        size_t base = (size_t)b * CHWN + (size_t)(n0 + row) * CN + o0 + seg * 16;
        *(uint4*)&g_Q8[base] = qv;
        *(uint4*)&g_K8[base] = kv;
    }
    // Q_mask flush
    {
        int c4 = tid >> 6;
        int nl = tid & 63;
        atomicMax(&g_QmaskU[c4 * HWN + n0 + nl], sRedU[tid]);
    }
}

// ---------------------------------------------------------------------------
// 3) scores + batch-softmax + m2 reduction  (int8 mma m16n8k32)
//    Block (m0,n0) covers h_k = m0/64 entirely, so the block reduces its
//    per-column maxes directly into g_m2[b*64 + blockIdx.x] — no colmax pass.
// ---------------------------------------------------------------------------
#define KC      64
#define PITCH   20
#define TILE32  (64 * PITCH)
#define OPST32  (4 * TILE32)
#define SK_BASE (2 * OPST32)
#define RED32   (4 * OPST32)
#define SCORES_SMEM_BYTES (RED32 * 4 + 256 * 4)
#define NCHUNK  (CN / KC)               // 4

__global__ __launch_bounds__(256, 2) void scores_kernel() {
    extern __shared__ uint32_t smem[];
    uint32_t* sQ = smem;
    uint32_t* sK = smem + SK_BASE;
    int* sRed = (int*)(smem + RED32);

    const uint32_t sQ_u = (uint32_t)__cvta_generic_to_shared(sQ);
    const uint32_t sK_u = (uint32_t)__cvta_generic_to_shared(sK);

    const int m0 = blockIdx.x * 64;
    const int n0 = blockIdx.y * 64;
    const int tid = threadIdx.x;
    const int warp = tid >> 5;
    const int lane = tid & 31;
    const int tg  = lane & 3;
    const int wn = warp & 3;
    const int wm = warp >> 2;

    sRed[tid] = 0;

    int acc[4][4][4];
#pragma unroll
    for (int b = 0; b < 4; b++)
#pragma unroll
        for (int j = 0; j < 4; j++)
#pragma unroll
            for (int e = 0; e < 4; e++) acc[b][j][e] = 0;

    const uint32_t a_off = (uint32_t)((wn * 16 + (lane & 15)) * 80 + (lane >> 4) * 16);
    const uint32_t b_off = (uint32_t)((wm * 32 + ((lane >> 4) << 3) + (lane & 7)) * 80 +
                                      ((lane >> 3) & 1) * 16);

    auto issue_chunk = [&](int c, int s) {
        const int kb = c * KC;
#pragma unroll
        for (int it = 0; it < 4; it++) {
            int slot = it * 256 + tid;
            int b   = slot >> 8;
            int row = (slot >> 2) & 63;
            int seg = slot & 3;
            int d = s * OPST32 + b * TILE32 + row * PITCH + seg * 4;
            cpasync16(&sQ[d], &g_Q8[(size_t)b * CHWN + (size_t)(n0 + row) * CN + kb + seg * 16]);
            cpasync16(&sK[d], &g_K8[(size_t)b * CHWN + (size_t)(m0 + row) * CN + kb + seg * 16]);
        }
    };

    issue_chunk(0, 0);
    cpcommit();

    for (int c = 0; c < NCHUNK; c++) {
        cpwait0();
        __syncthreads();
        if (c < NCHUNK - 1) { issue_chunk(c + 1, (c + 1) & 1); cpcommit(); }

        const int s = c & 1;
        const uint32_t qbase = sQ_u + (uint32_t)(s * OPST32 * 4);
        const uint32_t kbase = sK_u + (uint32_t)(s * OPST32 * 4);
#pragma unroll
        for (int kk = 0; kk < 2; kk++) {
            const uint32_t kbyte = kk * 32;
#pragma unroll
            for (int b = 0; b < 4; b++) {
                const uint32_t tb = (uint32_t)(b * TILE32 * 4);
                uint32_t A0, A1, A2, A3;
                ldmx4(A0, A1, A2, A3, qbase + tb + a_off + kbyte);
#pragma unroll
                for (int jp = 0; jp < 2; jp++) {
                    uint32_t B0, B1, B2, B3;
                    ldmx4(B0, B1, B2, B3, kbase + tb + b_off + jp * 1280 + kbyte);
                    const int j0 = jp * 2;
                    asm volatile(
                        "mma.sync.aligned.m16n8k32.row.col.s32.s8.s8.s32 "
                        "{%0,%1,%2,%3}, {%4,%5,%6,%7}, {%8,%9}, {%0,%1,%2,%3};"
                        : "+r"(acc[b][j0][0]), "+r"(acc[b][j0][1]),
                          "+r"(acc[b][j0][2]), "+r"(acc[b][j0][3])
                        : "r"(A0), "r"(A1), "r"(A2), "r"(A3), "r"(B0), "r"(B1));
                    asm volatile(
                        "mma.sync.aligned.m16n8k32.row.col.s32.s8.s8.s32 "
                        "{%0,%1,%2,%3}, {%4,%5,%6,%7}, {%8,%9}, {%0,%1,%2,%3};"
                        : "+r"(acc[b][j0+1][0]), "+r"(acc[b][j0+1][1]),
                          "+r"(acc[b][j0+1][2]), "+r"(acc[b][j0+1][3])
                        : "r"(A0), "r"(A1), "r"(A2), "r"(A3), "r"(B2), "r"(B3));
                }
            }
        }
    }

#pragma unroll
    for (int j = 0; j < 4; j++) {
#pragma unroll
        for (int p = 0; p < 2; p++) {
            float colv[4];
#pragma unroll
            for (int b = 0; b < 4; b++) colv[b] = 0.f;
#pragma unroll
            for (int rr = 0; rr < 2; rr++) {
                int e = rr * 2 + p;
                float sv[4];
                float mx = -3.4e38f;
#pragma unroll
                for (int b = 0; b < 4; b++) {
                    sv[b] = (float)acc[b][j][e] * DEQ;
                    mx = fmaxf(mx, sv[b]);
                }
                float ex[4], sum = 0.f;
#pragma unroll
                for (int b = 0; b < 4; b++) { ex[b] = __expf(sv[b] - mx); sum += ex[b]; }
                float inv = 1.0f / sum;
#pragma unroll
                for (int b = 0; b < 4; b++) colv[b] = fmaxf(colv[b], ex[b] * inv);
            }
            int m_local = wm * 32 + j * 8 + tg * 2 + p;
#pragma unroll
            for (int b = 0; b < 4; b++)
                atomicMax(&sRed[b * 64 + m_local], __float_as_int(colv[b]));
        }
    }
    __syncthreads();

    // reduce sRed[b][0:64] -> one value per b, atomicMax into g_m2[b*64 + h_k]
    if (warp < 4) {
        int b = warp;
        int v = max(sRed[b * 64 + lane], sRed[b * 64 + lane + 32]);
#pragma unroll
        for (int o = 16; o > 0; o >>= 1)
            v = max(v, __shfl_xor_sync(0xffffffffu, v, o));
        if (lane == 0)
            atomicMax((int*)&g_m2[b * HN + blockIdx.x], v);
    }
}

// ---------------------------------------------------------------------------
// 5) out[b,c,n] = V * (1 + m2[b*64 + c/4] * Qmask[(c%4)*4096 + n])
// ---------------------------------------------------------------------------
__global__ void out_kernel(float* __restrict__ out) {
    int f = blockIdx.x * blockDim.x + threadIdx.x;     // float4 index
    if (f >= BN * CHWN / 4) return;
    int n4 = f & (HWN / 4 - 1);
    int bc = f >> 10;
    int c  = bc & (CN - 1);
    int b  = bc >> 8;
    int n  = n4 * 4;
    float m2v = g_m2[b * 64 + (c >> 2)];
    uint4 qu = *reinterpret_cast<const uint4*>(&g_QmaskU[(c & 3) * HWN + n]);
    float4 qm = make_float4(funkey(qu.x), funkey(qu.y), funkey(qu.z), funkey(qu.w));
    float4 v  = reinterpret_cast<const float4*>(g_V)[f];
    float4 o;
    o.x = v.x * fmaf(m2v, qm.x, 1.0f);
    o.y = v.y * fmaf(m2v, qm.y, 1.0f);
    o.z = v.z * fmaf(m2v, qm.z, 1.0f);
    o.w = v.w * fmaf(m2v, qm.w, 1.0f);
    reinterpret_cast<float4*>(out)[f] = o;
}

// ---------------------------------------------------------------------------
extern "C" void kernel_launch(void* const* d_in, const int* in_sizes, int n_in,
                              void* d_out, int out_size) {
    const float* fuse = (const float*)d_in[0];
    const float* Wq   = (const float*)d_in[1];
    const float* bq   = (const float*)d_in[2];
    const float* Wk   = (const float*)d_in[3];
    const float* bk   = (const float*)d_in[4];
    const float* Wv   = (const float*)d_in[5];
    const float* bv   = (const float*)d_in[6];
    float* out = (float*)d_out;

    cudaFuncSetAttribute(scores_kernel,
                         cudaFuncAttributeMaxDynamicSharedMemorySize,
                         SCORES_SMEM_BYTES);
    cudaFuncSetAttribute(qkv_kernel,
                         cudaFuncAttributeMaxDynamicSharedMemorySize,
                         QKV_SMEM);

    init_kernel<<<(4 * HWN + 255) / 256, 256>>>();

    dim3 gq(HWN / 64, CN / 64, BN);
    qkv_kernel<<<gq, 256, QKV_SMEM>>>(fuse, Wq, bq, Wk, bk, Wv, bv);

    dim3 gs(HWN / 64, HWN / 64);
    scores_kernel<<<gs, 256, SCORES_SMEM_BYTES>>>();

    out_kernel<<<(BN * CHWN / 4 + 255) / 256, 256>>>(out);
}

// round 17
// speedup vs baseline: 1.0564x; 1.0564x over previous
#include <cuda_runtime.h>
#include <math.h>
#include <stdint.h>

// Problem constants
#define BN   4
#define CN   256
#define HN   64
#define WN   64
#define HWN  4096
#define CHWN (CN * HWN)     // 1048576
#define SCALE 0.0625f       // 1/sqrt(256)

// int8 quantization: Q,K in [-2,2] (6.2 sigma), 63.5 LSB per unit
#define QMUL 63.5f
#define DEQ  (SCALE / (QMUL * QMUL))   // fold 1/sqrt(C) into dequant

// ---------------------------------------------------------------------------
// Scratch (device globals; no allocations allowed)
// ---------------------------------------------------------------------------
__device__ float    g_V [BN * CHWN];         // fp32 V, [b][c][n]
__device__ uint8_t  g_Q8[BN * CHWN];         // int8 Q, TRANSPOSED [b][n][c]
__device__ uint8_t  g_K8[BN * CHWN];         // int8 K, TRANSPOSED [b][m][c]
__device__ uint32_t g_QmaskU[4 * HWN];       // order-keyed Q_mask, (c%4)*4096+n
__device__ float    g_m2[BN * HN];           // int-keyed positive floats, b*64+h_k

__device__ __forceinline__ void cpasync16(void* dst, const void* src) {
    unsigned s = (unsigned)__cvta_generic_to_shared(dst);
    asm volatile("cp.async.cg.shared.global [%0], [%1], 16;\n" :: "r"(s), "l"(src));
}
__device__ __forceinline__ void cpcommit() { asm volatile("cp.async.commit_group;\n"); }
__device__ __forceinline__ void cpwait0()  { asm volatile("cp.async.wait_group 0;\n"); }

__device__ __forceinline__ void ldmx4(uint32_t& r0, uint32_t& r1, uint32_t& r2, uint32_t& r3,
                                      uint32_t addr) {
    asm volatile("ldmatrix.sync.aligned.m8n8.x4.shared.b16 {%0,%1,%2,%3}, [%4];"
                 : "=r"(r0), "=r"(r1), "=r"(r2), "=r"(r3) : "r"(addr));
}

__device__ __forceinline__ uint32_t tf32c(float x) {
    uint32_t r;
    asm("cvt.rna.tf32.f32 %0, %1;" : "=r"(r) : "f"(x));
    return r;
}
__device__ __forceinline__ int q8(float x) {
    int v = __float2int_rn(x * QMUL);
    return max(-127, min(127, v));
}
// order-preserving float <-> uint key (handles negatives)
__device__ __forceinline__ uint32_t fkey(float f) {
    uint32_t b = __float_as_uint(f);
    return b ^ (uint32_t)(((int)b >> 31) | 0x80000000);
}
__device__ __forceinline__ float funkey(uint32_t u) {
    uint32_t b = (u & 0x80000000u) ? (u ^ 0x80000000u) : ~u;
    return __uint_as_float(b);
}

// ---------------------------------------------------------------------------
// 0) zero QmaskU and m2 each call (atomics accumulate into them)
// ---------------------------------------------------------------------------
__global__ void init_kernel() {
    int i = blockIdx.x * blockDim.x + threadIdx.x;
    if (i < 4 * HWN) g_QmaskU[i] = 0u;
    if (i < BN * HN)  g_m2[i] = 0.0f;
}

// ---------------------------------------------------------------------------
// 1) fused QKV 1x1-conv GEMM on tf32 tensor cores  (R15 version, measured good).
//    Block: 64(o) x 64(n) for one b, ALL 3 gemms (fuse tile shared as B).
//    8 warps = 4(o-tiles of 16) x 2(n-halves of 32); mma.m16n8k8.tf32.
//    Epilogue: V fp32 [c][n]; Q/K int8 transposed [n][c]; Q_mask reduce.
// ---------------------------------------------------------------------------
#define QKC  16
#define FPCH 72                          // fuse smem pitch (floats)
#define WPCH 20                          // W smem pitch (floats)
#define FST  (QKC * FPCH)                // 1152
#define WST  (64 * WPCH)                 // 1280 per gemm
#define QSTG (FST + 3 * WST)             // 4992 floats per stage
#define QKV_SMEM ((2 * QSTG + 256) * 4)

__global__ __launch_bounds__(256, 2) void qkv_kernel(
    const float* __restrict__ fuse,
    const float* __restrict__ Wq, const float* __restrict__ bq,
    const float* __restrict__ Wk, const float* __restrict__ bk,
    const float* __restrict__ Wv, const float* __restrict__ bv)
{
    extern __shared__ float smemf[];
    uint32_t* sRedU = (uint32_t*)(smemf + 2 * QSTG);   // [4][64]

    const int b  = blockIdx.z;
    const int o0 = blockIdx.y * 64;
    const int n0 = blockIdx.x * 64;
    const int tid = threadIdx.x;
    const int warp = tid >> 5;
    const int lane = tid & 31;
    const int gid = lane >> 2;    // 0..7
    const int tg  = lane & 3;     // 0..3
    const int wo = warp & 3;      // o-tile (16 rows each)
    const int wm = warp >> 2;     // n-half (32 cols each)

    sRedU[tid] = 0u;

    const float* Wg[3] = {Wq, Wk, Wv};

    float acc[3][4][4];           // [gemm][j(n8 tile)][e]
#pragma unroll
    for (int g = 0; g < 3; g++)
#pragma unroll
        for (int j = 0; j < 4; j++)
#pragma unroll
            for (int e = 0; e < 4; e++) acc[g][j][e] = 0.f;

    // ---- async load of one K-chunk (16 c) into stage s ----
    auto issue_chunk = [&](int c, int s) {
        const int c0 = c * QKC;
        float* stg = smemf + s * QSTG;
        {   // fuse tile [16 k][64 n]: 1 float4/thread
            int k  = tid >> 4;
            int n4 = (tid & 15) * 4;
            cpasync16(&stg[k * FPCH + n4],
                      &fuse[(size_t)b * CHWN + (size_t)(c0 + k) * HWN + n0 + n4]);
        }
        {   // W tiles [64 o][16 k] row-major, 1 float4/thread/gemm
            int o  = tid >> 2;
            int k4 = (tid & 3) * 4;
#pragma unroll
            for (int g = 0; g < 3; g++)
                cpasync16(&stg[FST + g * WST + o * WPCH + k4],
                          &Wg[g][(size_t)(o0 + o) * CN + c0 + k4]);
        }
    };

    issue_chunk(0, 0);
    cpcommit();

    const int arow  = wo * 16 + gid;
    const int bcol0 = wm * 32 + gid;

    for (int c = 0; c < CN / QKC; c++) {
        cpwait0();
        __syncthreads();
        if (c < CN / QKC - 1) { issue_chunk(c + 1, (c + 1) & 1); cpcommit(); }

        const float* stg = smemf + (c & 1) * QSTG;
        const float* sF  = stg;
        const float* sW  = stg + FST;
#pragma unroll
        for (int kk = 0; kk < QKC; kk += 8) {
            // B frags (fuse), shared across gemms
            uint32_t Bc[4][2];
#pragma unroll
            for (int j = 0; j < 4; j++) {
                Bc[j][0] = tf32c(sF[(kk + tg    ) * FPCH + bcol0 + j * 8]);
                Bc[j][1] = tf32c(sF[(kk + tg + 4) * FPCH + bcol0 + j * 8]);
            }
#pragma unroll
            for (int g = 0; g < 3; g++) {
                const float* w = sW + g * WST;
                uint32_t A0 = tf32c(w[(arow    ) * WPCH + kk + tg]);
                uint32_t A1 = tf32c(w[(arow + 8) * WPCH + kk + tg]);
                uint32_t A2 = tf32c(w[(arow    ) * WPCH + kk + tg + 4]);
                uint32_t A3 = tf32c(w[(arow + 8) * WPCH + kk + tg + 4]);
#pragma unroll
                for (int j = 0; j < 4; j++) {
                    asm volatile(
                        "mma.sync.aligned.m16n8k8.row.col.f32.tf32.tf32.f32 "
                        "{%0,%1,%2,%3}, {%4,%5,%6,%7}, {%8,%9}, {%0,%1,%2,%3};"
                        : "+f"(acc[g][j][0]), "+f"(acc[g][j][1]),
                          "+f"(acc[g][j][2]), "+f"(acc[g][j][3])
                        : "r"(A0), "r"(A1), "r"(A2), "r"(A3),
                          "r"(Bc[j][0]), "r"(Bc[j][1]));
                }
            }
        }
    }

    // ---- epilogue (R15: direct scattered stores) ----
    const int oA = o0 + wo * 16 + gid;     // e>>1 == 0 rows
    const int oB = oA + 8;                 // e>>1 == 1 rows
    const float bq0 = bq[oA], bq1 = bq[oB];
    const float bk0 = bk[oA], bk1 = bk[oB];
    const float bv0 = bv[oA], bv1 = bv[oB];
    const int cm = gid & 3;                // oA&3 == oB&3 == gid&3

#pragma unroll
    for (int j = 0; j < 4; j++) {
#pragma unroll
        for (int p = 0; p < 2; p++) {
            const int nl = wm * 32 + j * 8 + tg * 2 + p;   // n local
            const int n  = n0 + nl;
            float q0 = acc[0][j][p]     + bq0;
            float q1 = acc[0][j][2 + p] + bq1;
            float k0 = acc[1][j][p]     + bk0;
            float k1 = acc[1][j][2 + p] + bk1;
            float v0 = acc[2][j][p]     + bv0;
            float v1 = acc[2][j][2 + p] + bv1;
            // V fp32 [c][n]
            g_V[(size_t)b * CHWN + (size_t)oA * HWN + n] = v0;
            g_V[(size_t)b * CHWN + (size_t)oB * HWN + n] = v1;
            // Q/K int8 transposed [n][c]
            size_t t = (size_t)b * CHWN + (size_t)n * CN;
            g_Q8[t + oA] = (uint8_t)(q8(q0) & 0xFF);
            g_Q8[t + oB] = (uint8_t)(q8(q1) & 0xFF);
            g_K8[t + oA] = (uint8_t)(q8(k0) & 0xFF);
            g_K8[t + oB] = (uint8_t)(q8(k1) & 0xFF);
            // Q_mask block reduce (signed-safe key)
            atomicMax(&sRedU[cm * 64 + nl], fkey(fmaxf(q0, q1)));
        }
    }
    __syncthreads();

    {
        int c4 = tid >> 6;
        int nl = tid & 63;
        atomicMax(&g_QmaskU[c4 * HWN + n0 + nl], sRedU[tid]);
    }
}

// ---------------------------------------------------------------------------
// 3) scores + batch-softmax + m2 reduction  (int8 mma m16n8k32)
//    Block (m0,n0) covers h_k = m0/64 entirely, so the block reduces its
//    per-column maxes directly into g_m2[b*64 + blockIdx.x] — no colmax pass.
// ---------------------------------------------------------------------------
#define KC      64
#define PITCH   20
#define TILE32  (64 * PITCH)
#define OPST32  (4 * TILE32)
#define SK_BASE (2 * OPST32)
#define RED32   (4 * OPST32)
#define SCORES_SMEM_BYTES (RED32 * 4 + 256 * 4)
#define NCHUNK  (CN / KC)               // 4

__global__ __launch_bounds__(256, 2) void scores_kernel() {
    extern __shared__ uint32_t smem[];
    uint32_t* sQ = smem;
    uint32_t* sK = smem + SK_BASE;
    int* sRed = (int*)(smem + RED32);

    const uint32_t sQ_u = (uint32_t)__cvta_generic_to_shared(sQ);
    const uint32_t sK_u = (uint32_t)__cvta_generic_to_shared(sK);

    const int m0 = blockIdx.x * 64;
    const int n0 = blockIdx.y * 64;
    const int tid = threadIdx.x;
    const int warp = tid >> 5;
    const int lane = tid & 31;
    const int tg  = lane & 3;
    const int wn = warp & 3;
    const int wm = warp >> 2;

    sRed[tid] = 0;

    int acc[4][4][4];
#pragma unroll
    for (int b = 0; b < 4; b++)
#pragma unroll
        for (int j = 0; j < 4; j++)
#pragma unroll
            for (int e = 0; e < 4; e++) acc[b][j][e] = 0;

    const uint32_t a_off = (uint32_t)((wn * 16 + (lane & 15)) * 80 + (lane >> 4) * 16);
    const uint32_t b_off = (uint32_t)((wm * 32 + ((lane >> 4) << 3) + (lane & 7)) * 80 +
                                      ((lane >> 3) & 1) * 16);

    auto issue_chunk = [&](int c, int s) {
        const int kb = c * KC;
#pragma unroll
        for (int it = 0; it < 4; it++) {
            int slot = it * 256 + tid;
            int b   = slot >> 8;
            int row = (slot >> 2) & 63;
            int seg = slot & 3;
            int d = s * OPST32 + b * TILE32 + row * PITCH + seg * 4;
            cpasync16(&sQ[d], &g_Q8[(size_t)b * CHWN + (size_t)(n0 + row) * CN + kb + seg * 16]);
            cpasync16(&sK[d], &g_K8[(size_t)b * CHWN + (size_t)(m0 + row) * CN + kb + seg * 16]);
        }
    };

    issue_chunk(0, 0);
    cpcommit();

    for (int c = 0; c < NCHUNK; c++) {
        cpwait0();
        __syncthreads();
        if (c < NCHUNK - 1) { issue_chunk(c + 1, (c + 1) & 1); cpcommit(); }

        const int s = c & 1;
        const uint32_t qbase = sQ_u + (uint32_t)(s * OPST32 * 4);
        const uint32_t kbase = sK_u + (uint32_t)(s * OPST32 * 4);
#pragma unroll
        for (int kk = 0; kk < 2; kk++) {
            const uint32_t kbyte = kk * 32;
#pragma unroll
            for (int b = 0; b < 4; b++) {
                const uint32_t tb = (uint32_t)(b * TILE32 * 4);
                uint32_t A0, A1, A2, A3;
                ldmx4(A0, A1, A2, A3, qbase + tb + a_off + kbyte);
#pragma unroll
                for (int jp = 0; jp < 2; jp++) {
                    uint32_t B0, B1, B2, B3;
                    ldmx4(B0, B1, B2, B3, kbase + tb + b_off + jp * 1280 + kbyte);
                    const int j0 = jp * 2;
                    asm volatile(
                        "mma.sync.aligned.m16n8k32.row.col.s32.s8.s8.s32 "
                        "{%0,%1,%2,%3}, {%4,%5,%6,%7}, {%8,%9}, {%0,%1,%2,%3};"
                        : "+r"(acc[b][j0][0]), "+r"(acc[b][j0][1]),
                          "+r"(acc[b][j0][2]), "+r"(acc[b][j0][3])
                        : "r"(A0), "r"(A1), "r"(A2), "r"(A3), "r"(B0), "r"(B1));
                    asm volatile(
                        "mma.sync.aligned.m16n8k32.row.col.s32.s8.s8.s32 "
                        "{%0,%1,%2,%3}, {%4,%5,%6,%7}, {%8,%9}, {%0,%1,%2,%3};"
                        : "+r"(acc[b][j0+1][0]), "+r"(acc[b][j0+1][1]),
                          "+r"(acc[b][j0+1][2]), "+r"(acc[b][j0+1][3])
                        : "r"(A0), "r"(A1), "r"(A2), "r"(A3), "r"(B2), "r"(B3));
                }
            }
        }
    }

#pragma unroll
    for (int j = 0; j < 4; j++) {
#pragma unroll
        for (int p = 0; p < 2; p++) {
            float colv[4];
#pragma unroll
            for (int b = 0; b < 4; b++) colv[b] = 0.f;
#pragma unroll
            for (int rr = 0; rr < 2; rr++) {
                int e = rr * 2 + p;
                float sv[4];
                float mx = -3.4e38f;
#pragma unroll
                for (int b = 0; b < 4; b++) {
                    sv[b] = (float)acc[b][j][e] * DEQ;
                    mx = fmaxf(mx, sv[b]);
                }
                float ex[4], sum = 0.f;
#pragma unroll
                for (int b = 0; b < 4; b++) { ex[b] = __expf(sv[b] - mx); sum += ex[b]; }
                float inv = 1.0f / sum;
#pragma unroll
                for (int b = 0; b < 4; b++) colv[b] = fmaxf(colv[b], ex[b] * inv);
            }
            int m_local = wm * 32 + j * 8 + tg * 2 + p;
#pragma unroll
            for (int b = 0; b < 4; b++)
                atomicMax(&sRed[b * 64 + m_local], __float_as_int(colv[b]));
        }
    }
    __syncthreads();

    // reduce sRed[b][0:64] -> one value per b, atomicMax into g_m2[b*64 + h_k]
    if (warp < 4) {
        int b = warp;
        int v = max(sRed[b * 64 + lane], sRed[b * 64 + lane + 32]);
#pragma unroll
        for (int o = 16; o > 0; o >>= 1)
            v = max(v, __shfl_xor_sync(0xffffffffu, v, o));
        if (lane == 0)
            atomicMax((int*)&g_m2[b * HN + blockIdx.x], v);
    }
}

// ---------------------------------------------------------------------------
// 5) out[b,c,n] = V * (1 + m2[b*64 + c/4] * Qmask[(c%4)*4096 + n])
// ---------------------------------------------------------------------------
__global__ void out_kernel(float* __restrict__ out) {
    int f = blockIdx.x * blockDim.x + threadIdx.x;     // float4 index
    if (f >= BN * CHWN / 4) return;
    int n4 = f & (HWN / 4 - 1);
    int bc = f >> 10;
    int c  = bc & (CN - 1);
    int b  = bc >> 8;
    int n  = n4 * 4;
    float m2v = g_m2[b * 64 + (c >> 2)];
    uint4 qu = *reinterpret_cast<const uint4*>(&g_QmaskU[(c & 3) * HWN + n]);
    float4 qm = make_float4(funkey(qu.x), funkey(qu.y), funkey(qu.z), funkey(qu.w));
    float4 v  = reinterpret_cast<const float4*>(g_V)[f];
    float4 o;
    o.x = v.x * fmaf(m2v, qm.x, 1.0f);
    o.y = v.y * fmaf(m2v, qm.y, 1.0f);
    o.z = v.z * fmaf(m2v, qm.z, 1.0f);
    o.w = v.w * fmaf(m2v, qm.w, 1.0f);
    reinterpret_cast<float4*>(out)[f] = o;
}

// ---------------------------------------------------------------------------
extern "C" void kernel_launch(void* const* d_in, const int* in_sizes, int n_in,
                              void* d_out, int out_size) {
    const float* fuse = (const float*)d_in[0];
    const float* Wq   = (const float*)d_in[1];
    const float* bq   = (const float*)d_in[2];
    const float* Wk   = (const float*)d_in[3];
    const float* bk   = (const float*)d_in[4];
    const float* Wv   = (const float*)d_in[5];
    const float* bv   = (const float*)d_in[6];
    float* out = (float*)d_out;

    cudaFuncSetAttribute(scores_kernel,
                         cudaFuncAttributeMaxDynamicSharedMemorySize,
                         SCORES_SMEM_BYTES);
    cudaFuncSetAttribute(qkv_kernel,
                         cudaFuncAttributeMaxDynamicSharedMemorySize,
                         QKV_SMEM);

    init_kernel<<<(4 * HWN + 255) / 256, 256>>>();

    dim3 gq(HWN / 64, CN / 64, BN);
    qkv_kernel<<<gq, 256, QKV_SMEM>>>(fuse, Wq, bq, Wk, bk, Wv, bv);

    dim3 gs(HWN / 64, HWN / 64);
    scores_kernel<<<gs, 256, SCORES_SMEM_BYTES>>>();

    out_kernel<<<(BN * CHWN / 4 + 255) / 256, 256>>>(out);
}